// round 15
// baseline (speedup 1.0000x reference)
#include <cuda_runtime.h>
#include <cuda_fp16.h>
#include <math.h>
#include <stdint.h>

// Problem constants
#define SEQ     8192
#define BATCH   2
#define MTOT    (BATCH * SEQ)   // 16384
#define HIDDEN  768
#define KV      256
#define DMAX    7
#define NSM     148

// Scratch (static __device__ — no runtime allocation allowed)
__device__ float g_e[DMAX + 1];
__device__ __align__(16) __half g_vh[MTOT * KV];         // gemm1 out (fp16)
__device__ __align__(16) __half g_ah[MTOT * KV];         // smooth out (fp16)
__device__ __align__(16) __half g_xh[MTOT * HIDDEN];     // x in fp16
__device__ __align__(16) __half g_wvh[KV * HIDDEN];      // Wv in fp16
__device__ __align__(16) __half g_woh[HIDDEN * KV];      // Wo in fp16

// ---------------------------------------------------------------------------
// helpers
// ---------------------------------------------------------------------------
__device__ __forceinline__ uint32_t smem_u32(const void* p) {
    uint32_t a;
    asm("{ .reg .u64 t; cvta.to.shared.u64 t, %1; cvt.u32.u64 %0, t; }"
        : "=r"(a) : "l"(p));
    return a;
}

__device__ __forceinline__ void ldsm4(uint32_t* r, uint32_t addr) {
    asm volatile("ldmatrix.sync.aligned.m8n8.x4.shared.b16 {%0,%1,%2,%3}, [%4];"
        : "=r"(r[0]), "=r"(r[1]), "=r"(r[2]), "=r"(r[3]) : "r"(addr));
}

__device__ __forceinline__ void mma_f16(float* d, const uint32_t* a,
                                        const uint32_t* b) {
    asm volatile(
        "mma.sync.aligned.m16n8k16.row.col.f32.f16.f16.f32 "
        "{%0,%1,%2,%3}, {%4,%5,%6,%7}, {%8,%9}, {%0,%1,%2,%3};"
        : "+f"(d[0]), "+f"(d[1]), "+f"(d[2]), "+f"(d[3])
        : "r"(a[0]), "r"(a[1]), "r"(a[2]), "r"(a[3]), "r"(b[0]), "r"(b[1]));
}

#define CP_ASYNC16(dst, src) \
    asm volatile("cp.async.cg.shared.global [%0], [%1], 16;" \
                 :: "r"(dst), "l"(src) : "memory")
#define CP_COMMIT() asm volatile("cp.async.commit_group;" ::: "memory")
#define CP_WAIT0()  asm volatile("cp.async.wait_group 0;" ::: "memory")

// fp16 tile geometry: BK=128 -> 256B rows (128 fp16), 16 chunks of 16B.
// Swizzle: low 3 bits of chunk index XOR row&7 (conflict-free for ldmatrix:
// 8 rows sharing kg -> 8 distinct chunks in one 128B bank cycle); bit 3 of
// kg selects the 128B half untouched.
#define ASZH   (256 * 256)                // A tile bytes: 65536
#define BSZH   (128 * 256)                // B tile bytes: 32768
#define STGH   (ASZH + BSZH)              // 98304 per stage
#define NSTAGE 2                          // 192 KB total

__device__ __forceinline__ uint32_t swz(int row, int kg) {
    return (uint32_t)(row * 256) + ((uint32_t)(kg & 8) << 4) +
           ((uint32_t)((kg ^ row) & 7) << 4);
}

// ---------------------------------------------------------------------------
// Persistent-CTA FP16 GEMM (NT): C[m,n] = sum_k A[m*K+k]*B[n*K+k]
// fp16 in (pre-converted); HALF_OUT selects fp16 vs fp32 output.
// CTA tile 256x128, 512 threads (16 warps 4x4), warp tile 64x32, m16n8k16,
// BK=128 per chunk (256 MMAs... 128 MMAs + 48 LDSM per warp per barrier).
// 2-stage cp.async ping-pong: wait_group 0 + sync at chunk top, refill the
// just-freed stage with chunk c+1 (guarded to c>=1; prologue loads 0,1).
// K multiple of 128.
// ---------------------------------------------------------------------------
template <bool HALF_OUT>
__global__ __launch_bounds__(512, 1) void gemm_fp16(
    const __half* __restrict__ A, const __half* __restrict__ B,
    void* __restrict__ Cv, int M, int N, int K)
{
    extern __shared__ char dynsmem[];
    const uint32_t sb = (smem_u32(dynsmem) + 127u) & ~127u;

    const int tid  = threadIdx.x;
    const int wid  = tid >> 5;
    const int lane = tid & 31;
    const int NC   = K >> 7;                 // 128-wide K chunks
    const int nTilesN = N >> 7;
    const int nTiles  = (M >> 8) * nTilesN;

    const int warpM = (wid >> 2) * 64;
    const int warpN = (wid & 3) * 32;

    // cp.async mapping (tile-relative)
    const int ra = tid >> 1, ha = tid & 1;     // A: 2 thr/row, 8x16B each
    const int rb = tid >> 2, qb = tid & 3;     // B: 4 thr/row, 4x16B each
    uint32_t dAo[8], dBo[4];
#pragma unroll
    for (int i = 0; i < 8; ++i) dAo[i] = swz(ra, ha * 8 + i);
#pragma unroll
    for (int i = 0; i < 4; ++i) dBo[i] = swz(rb, qb * 4 + i);

    // ldmatrix lane components
    const int laRow = warpM + (lane & 15);
    const int laKg  = lane >> 4;
    const int lbRow = warpN + (lane & 7) + ((lane & 16) >> 1);
    const int lbKg  = (lane >> 3) & 1;

#define ISSUE_STAGE(stg, kt)                                              \
    do {                                                                  \
        uint32_t bs = sb + (uint32_t)(stg) * STGH;                        \
        const __half* pa = gA + (kt);                                     \
        const __half* pb = gB + (kt);                                     \
        _Pragma("unroll")                                                 \
        for (int i = 0; i < 8; ++i) CP_ASYNC16(bs + dAo[i], pa + 8 * i);  \
        _Pragma("unroll")                                                 \
        for (int i = 0; i < 4; ++i)                                       \
            CP_ASYNC16(bs + ASZH + dBo[i], pb + 8 * i);                   \
        CP_COMMIT();                                                      \
    } while (0)

    for (int t = blockIdx.x; t < nTiles; t += gridDim.x) {
        const int bm = (t / nTilesN) * 256;
        const int bn = (t - (t / nTilesN) * nTilesN) * 128;

        const __half* gA = A + (size_t)(bm + ra) * K + ha * 64;
        const __half* gB = B + (size_t)(bn + rb) * K + qb * 32;

        float acc[4][4][4];
#pragma unroll
        for (int i = 0; i < 4; ++i)
#pragma unroll
            for (int j = 0; j < 4; ++j)
#pragma unroll
                for (int q = 0; q < 4; ++q) acc[i][j][q] = 0.f;

        ISSUE_STAGE(0, 0);
        if (NC > 1) ISSUE_STAGE(1, 128);

        for (int c = 0; c < NC; ++c) {
            CP_WAIT0();        // chunk c's data resident (all groups drained)
            __syncthreads();   // + chunk c-1 reads complete on all warps

            // refill the stage freed by chunk c-1 with chunk c+1
            if (c >= 1 && c + 1 < NC)
                ISSUE_STAGE((c + 1) & 1, (c + 1) * 128);

            const uint32_t sA = sb + (uint32_t)(c & 1) * STGH;
            const uint32_t sB = sA + ASZH;

            uint32_t af[2][4][4], bf[2][2][4];
#pragma unroll
            for (int mt = 0; mt < 4; ++mt)
                ldsm4(af[0][mt], sA + swz(laRow + mt * 16, laKg));
            ldsm4(bf[0][0], sB + swz(lbRow,      lbKg));
            ldsm4(bf[0][1], sB + swz(lbRow + 16, lbKg));

#pragma unroll
            for (int ks = 0; ks < 8; ++ks) {
                const int cur = ks & 1;
                if (ks < 7) {
                    const int kg = 2 * (ks + 1);
#pragma unroll
                    for (int mt = 0; mt < 4; ++mt)
                        ldsm4(af[cur ^ 1][mt],
                              sA + swz(laRow + mt * 16, kg + laKg));
                    ldsm4(bf[cur ^ 1][0], sB + swz(lbRow,      kg + lbKg));
                    ldsm4(bf[cur ^ 1][1], sB + swz(lbRow + 16, kg + lbKg));
                }
#pragma unroll
                for (int mt = 0; mt < 4; ++mt)
#pragma unroll
                    for (int nt = 0; nt < 4; ++nt)
                        mma_f16(acc[mt][nt], af[cur][mt],
                                &bf[cur][nt >> 1][(nt & 1) * 2]);
            }
        }

        // epilogue
#pragma unroll
        for (int mt = 0; mt < 4; ++mt) {
#pragma unroll
            for (int nt = 0; nt < 4; ++nt) {
                int row = bm + warpM + mt * 16 + (lane >> 2);
                int col = bn + warpN + nt * 8 + (lane & 3) * 2;
                if (HALF_OUT) {
                    __half* C = (__half*)Cv;
                    __half2 h0 = __floats2half2_rn(acc[mt][nt][0], acc[mt][nt][1]);
                    __half2 h1 = __floats2half2_rn(acc[mt][nt][2], acc[mt][nt][3]);
                    *reinterpret_cast<__half2*>(C + (size_t)row * N + col) = h0;
                    *reinterpret_cast<__half2*>(C + (size_t)(row + 8) * N + col) = h1;
                } else {
                    float* C = (float*)Cv;
                    float2 v0 = make_float2(acc[mt][nt][0], acc[mt][nt][1]);
                    float2 v1 = make_float2(acc[mt][nt][2], acc[mt][nt][3]);
                    *reinterpret_cast<float2*>(C + (size_t)row * N + col) = v0;
                    *reinterpret_cast<float2*>(C + (size_t)(row + 8) * N + col) = v1;
                }
            }
        }
        __syncthreads();   // tile transition: reads done before next prologue
    }
#undef ISSUE_STAGE
}

// ---------------------------------------------------------------------------
// Kernel 0: fused prologue.
// Block 0: coefficients. Blocks 1..768: weights -> fp16. Rest: x -> fp16
// (8 elements / thread, 16B stores).
// ---------------------------------------------------------------------------
#define WBLK (KV * HIDDEN / 256)            // 768
#define XBLK (MTOT * HIDDEN / 2048)         // 6144

__global__ void pre_kernel(const float* __restrict__ x,
                           const float* __restrict__ Wv,
                           const float* __restrict__ Wo) {
    const int b = blockIdx.x;
    if (b == 0) {
        __shared__ float warp_sum[8];
        const int t = threadIdx.x;
        const int lane = t & 31, warp = t >> 5;
        const float cc = -logf(10000.0f) / 384.0f;
        for (int d = 0; d <= DMAX; ++d) {
            float val = 0.f;
            for (int j = t; j < 384; j += 256)
                val += cosf((float)d * __expf(cc * (float)j));
#pragma unroll
            for (int o = 16; o; o >>= 1)
                val += __shfl_xor_sync(0xffffffffu, val, o);
            if (lane == 0) warp_sum[warp] = val;
            __syncthreads();
            if (t == 0) {
                float w = 0.f;
#pragma unroll
                for (int i = 0; i < 8; ++i) w += warp_sum[i];
                g_e[d] = expf(w - 384.0f);
            }
            __syncthreads();
        }
    } else if (b <= WBLK) {
        int i = (b - 1) * 256 + threadIdx.x;
        g_wvh[i] = __float2half_rn(Wv[i]);
        g_woh[i] = __float2half_rn(Wo[i]);
    } else {
        int i = (b - 1 - WBLK) * 2048 + threadIdx.x * 8;
        float4 v0 = *reinterpret_cast<const float4*>(x + i);
        float4 v1 = *reinterpret_cast<const float4*>(x + i + 4);
        __half2 h0 = __floats2half2_rn(v0.x, v0.y);
        __half2 h1 = __floats2half2_rn(v0.z, v0.w);
        __half2 h2 = __floats2half2_rn(v1.x, v1.y);
        __half2 h3 = __floats2half2_rn(v1.z, v1.w);
        uint4 o;
        o.x = *reinterpret_cast<uint32_t*>(&h0);
        o.y = *reinterpret_cast<uint32_t*>(&h1);
        o.z = *reinterpret_cast<uint32_t*>(&h2);
        o.w = *reinterpret_cast<uint32_t*>(&h3);
        *reinterpret_cast<uint4*>(g_xh + i) = o;
    }
}

// ---------------------------------------------------------------------------
// Kernel 2: softmax == normalized 15-tap convolution along seq (fp16 IO).
// Sliding window: 4 consecutive rows x 4 cols per thread; fp32 accumulate.
// ---------------------------------------------------------------------------
__global__ __launch_bounds__(256) void smooth_kernel() {
    const int NCG = KV / 4;                       // 64 col-groups of 4
    int idx = blockIdx.x * blockDim.x + threadIdx.x;
    if (idx >= (MTOT / 4) * NCG) return;
    const int mg = idx >> 6;
    const int c4 = (idx & 63) * 4;
    const int m0 = mg << 2;
    const int s0 = m0 & (SEQ - 1);

    float earr[15];
#pragma unroll
    for (int t = 0; t < 15; ++t) earr[t] = g_e[t < 7 ? 7 - t : t - 7];

    uint2 w[18];   // 4 fp16 per row
#pragma unroll
    for (int j = 0; j < 18; ++j) {
        int s = s0 - 7 + j;
        if (s >= 0 && s < SEQ)
            w[j] = *reinterpret_cast<const uint2*>(
                g_vh + (size_t)(m0 - 7 + j) * KV + c4);
        else
            w[j] = make_uint2(0u, 0u);
    }

#pragma unroll
    for (int i = 0; i < 4; ++i) {
        const int s = s0 + i;
        float acc[4] = {0.f, 0.f, 0.f, 0.f};
#pragma unroll
        for (int t = 0; t < 15; ++t) {
            const float e = earr[t];
            const uint32_t* uw = reinterpret_cast<const uint32_t*>(&w[i + t]);
#pragma unroll
            for (int p = 0; p < 2; ++p) {
                __half2 hh;
                *reinterpret_cast<uint32_t*>(&hh) = uw[p];
                float2 f = __half22float2(hh);
                acc[p * 2 + 0] += e * f.x;
                acc[p * 2 + 1] += e * f.y;
            }
        }
        float z = 1.0f;
#pragma unroll
        for (int d = 1; d <= DMAX; ++d) {
            if (s >= d)       z += g_e[d];
            if (s + d < SEQ)  z += g_e[d];
        }
        const float inv = 1.0f / z;
        __half2 o0 = __floats2half2_rn(acc[0] * inv, acc[1] * inv);
        __half2 o1 = __floats2half2_rn(acc[2] * inv, acc[3] * inv);
        uint2 o;
        o.x = *reinterpret_cast<uint32_t*>(&o0);
        o.y = *reinterpret_cast<uint32_t*>(&o1);
        *reinterpret_cast<uint2*>(g_ah + (size_t)(m0 + i) * KV + c4) = o;
    }
}

// ---------------------------------------------------------------------------
// Launch
// ---------------------------------------------------------------------------
extern "C" void kernel_launch(void* const* d_in, const int* in_sizes, int n_in,
                              void* d_out, int out_size) {
    const float* x  = (const float*)d_in[0];
    // d_in[1] = Wq, d_in[2] = Wk are dead (rope ignores its input)
    const float* Wv = (const float*)d_in[3];
    const float* Wo = (const float*)d_in[4];
    float* out = (float*)d_out;

    __half* vh_buf; cudaGetSymbolAddress((void**)&vh_buf, g_vh);
    __half* ah_buf; cudaGetSymbolAddress((void**)&ah_buf, g_ah);
    __half* xh_buf; cudaGetSymbolAddress((void**)&xh_buf, g_xh);
    __half* wv_buf; cudaGetSymbolAddress((void**)&wv_buf, g_wvh);
    __half* wo_buf; cudaGetSymbolAddress((void**)&wo_buf, g_woh);

    const int SMEM_BYTES = NSTAGE * STGH + 128;   // ~192 KB
    cudaFuncSetAttribute(gemm_fp16<true>,
                         cudaFuncAttributeMaxDynamicSharedMemorySize, SMEM_BYTES);
    cudaFuncSetAttribute(gemm_fp16<false>,
                         cudaFuncAttributeMaxDynamicSharedMemorySize, SMEM_BYTES);

    // 0) coefficients + fp16 pre-conversion of Wv, Wo, x (one launch)
    pre_kernel<<<1 + WBLK + XBLK, 256>>>(x, Wv, Wo);

    // 1) v = x @ Wv^T -> fp16  (tiles = 128, K=768 -> NC=6)
    gemm_fp16<true><<<128, 512, SMEM_BYTES>>>(xh_buf, wv_buf, vh_buf,
                                              MTOT, KV, HIDDEN);

    // 2) softmax(attn) @ v == normalized 15-tap convolution (fp16 -> fp16)
    {
        int n = (MTOT / 4) * (KV / 4);
        smooth_kernel<<<(n + 255) / 256, 256>>>();
    }

    // 3) out = a @ Wo^T -> fp32 (tiles = 384, persistent, K=256 -> NC=2)
    gemm_fp16<false><<<NSM, 512, SMEM_BYTES>>>(ah_buf, wo_buf, out,
                                               MTOT, HIDDEN, KV);
}

// round 16
// speedup vs baseline: 1.1151x; 1.1151x over previous
#include <cuda_runtime.h>
#include <cuda_fp16.h>
#include <math.h>
#include <stdint.h>

// Problem constants
#define SEQ     8192
#define BATCH   2
#define MTOT    (BATCH * SEQ)   // 16384
#define HIDDEN  768
#define KV      256
#define DMAX    7
#define NSM     148

// Scratch (static __device__ — no runtime allocation allowed)
__device__ float g_e[DMAX + 1];
__device__ __align__(16) __half g_vh[MTOT * KV];         // gemm1 out (fp16)
__device__ __align__(16) __half g_ah[MTOT * KV];         // smooth out (fp16)
__device__ __align__(16) __half g_xh[MTOT * HIDDEN];     // x in fp16
__device__ __align__(16) __half g_wvh[KV * HIDDEN];      // Wv in fp16
__device__ __align__(16) __half g_woh[HIDDEN * KV];      // Wo in fp16

// ---------------------------------------------------------------------------
// helpers
// ---------------------------------------------------------------------------
__device__ __forceinline__ uint32_t smem_u32(const void* p) {
    uint32_t a;
    asm("{ .reg .u64 t; cvta.to.shared.u64 t, %1; cvt.u32.u64 %0, t; }"
        : "=r"(a) : "l"(p));
    return a;
}

__device__ __forceinline__ void ldsm4(uint32_t* r, uint32_t addr) {
    asm volatile("ldmatrix.sync.aligned.m8n8.x4.shared.b16 {%0,%1,%2,%3}, [%4];"
        : "=r"(r[0]), "=r"(r[1]), "=r"(r[2]), "=r"(r[3]) : "r"(addr));
}

__device__ __forceinline__ void mma_f16(float* d, const uint32_t* a,
                                        const uint32_t* b) {
    asm volatile(
        "mma.sync.aligned.m16n8k16.row.col.f32.f16.f16.f32 "
        "{%0,%1,%2,%3}, {%4,%5,%6,%7}, {%8,%9}, {%0,%1,%2,%3};"
        : "+f"(d[0]), "+f"(d[1]), "+f"(d[2]), "+f"(d[3])
        : "r"(a[0]), "r"(a[1]), "r"(a[2]), "r"(a[3]), "r"(b[0]), "r"(b[1]));
}

#define CP_ASYNC16(dst, src) \
    asm volatile("cp.async.cg.shared.global [%0], [%1], 16;" \
                 :: "r"(dst), "l"(src) : "memory")
#define CP_COMMIT() asm volatile("cp.async.commit_group;" ::: "memory")
#define CP_WAIT1()  asm volatile("cp.async.wait_group 1;" ::: "memory")
#define CP_WAIT0()  asm volatile("cp.async.wait_group 0;" ::: "memory")

// fp16 tile geometry: BK=64 -> 128B rows (64 fp16), 8-group XOR swizzle.
// 128x128 CTA tile: A = B = 128 rows x 128B = 16 KB each.
#define ASZH   (128 * 128)                // A tile bytes: 16384
#define BSZH   (128 * 128)                // B tile bytes: 16384
#define STGH   (ASZH + BSZH)              // 32768 per stage
#define NSTAGE 3                          // 96 KB per CTA (2 CTAs/SM fit)

__device__ __forceinline__ uint32_t swz(int row, int kg) {
    return (uint32_t)(row * 128) + ((uint32_t)((kg ^ row) & 7) << 4);
}

// ---------------------------------------------------------------------------
// Persistent-CTA FP16 GEMM (NT): C[m,n] = sum_k A[m*K+k]*B[n*K+k]
// fp16 in (pre-converted); HALF_OUT selects fp16 vs fp32 output.
// CTA tile 128x128, 256 threads (8 warps 2x4), warp tile 64x32, m16n8k16,
// BK=64 per chunk. 2 CTAs/SM -> cross-CTA overlap of prologue/epilogue and
// single-wave gemm1 (256 tiles over 296 slots).
// 3-stage cp.async pipeline (prefetch distance 2, wait_group 1), one
// __syncthreads per chunk + one per tile transition. K multiple of 64.
// ---------------------------------------------------------------------------
template <bool HALF_OUT>
__global__ __launch_bounds__(256, 2) void gemm_fp16(
    const __half* __restrict__ A, const __half* __restrict__ B,
    void* __restrict__ Cv, int M, int N, int K)
{
    extern __shared__ char dynsmem[];
    const uint32_t sb = (smem_u32(dynsmem) + 127u) & ~127u;

    const int tid  = threadIdx.x;
    const int wid  = tid >> 5;
    const int lane = tid & 31;
    const int NC   = K >> 6;
    const int nTilesN = N >> 7;
    const int nTiles  = (M >> 7) * nTilesN;

    const int warpM = (wid >> 2) * 64;   // 0 or 64
    const int warpN = (wid & 3) * 32;    // 0..96

    // cp.async mapping: 2 thr/row (128 rows), each thread 64B = 4x16B
    const int ra = tid >> 1, ha = tid & 1;
    uint32_t dOf[4];
#pragma unroll
    for (int i = 0; i < 4; ++i) dOf[i] = swz(ra, ha * 4 + i);

    // ldmatrix lane components
    const int laRow = warpM + (lane & 15);
    const int laKg  = lane >> 4;
    const int lbRow = warpN + (lane & 7) + ((lane & 16) >> 1);
    const int lbKg  = (lane >> 3) & 1;

#define ISSUE_STAGE(stg, kt)                                              \
    do {                                                                  \
        uint32_t bs = sb + (uint32_t)(stg) * STGH;                        \
        const __half* pa = gA + (kt);                                     \
        const __half* pb = gB + (kt);                                     \
        CP_ASYNC16(bs + dOf[0], pa);                                      \
        CP_ASYNC16(bs + dOf[1], pa + 8);                                  \
        CP_ASYNC16(bs + dOf[2], pa + 16);                                 \
        CP_ASYNC16(bs + dOf[3], pa + 24);                                 \
        CP_ASYNC16(bs + ASZH + dOf[0], pb);                               \
        CP_ASYNC16(bs + ASZH + dOf[1], pb + 8);                           \
        CP_ASYNC16(bs + ASZH + dOf[2], pb + 16);                          \
        CP_ASYNC16(bs + ASZH + dOf[3], pb + 24);                          \
        CP_COMMIT();                                                      \
    } while (0)

    for (int t = blockIdx.x; t < nTiles; t += gridDim.x) {
        const int bm = (t / nTilesN) * 128;
        const int bn = (t - (t / nTilesN) * nTilesN) * 128;

        const __half* gA = A + (size_t)(bm + ra) * K + ha * 32;
        const __half* gB = B + (size_t)(bn + ra) * K + ha * 32;

        float acc[4][4][4];
#pragma unroll
        for (int i = 0; i < 4; ++i)
#pragma unroll
            for (int j = 0; j < 4; ++j)
#pragma unroll
                for (int q = 0; q < 4; ++q) acc[i][j][q] = 0.f;

        ISSUE_STAGE(0, 0);
        ISSUE_STAGE(1, 64);

        int stage = 0;
        for (int c = 0; c < NC; ++c) {
            CP_WAIT1();
            __syncthreads();

            if (c + 2 < NC) {
                int ns = stage + 2; if (ns >= NSTAGE) ns -= NSTAGE;
                ISSUE_STAGE(ns, (c + 2) * 64);
            }

            const uint32_t sA = sb + (uint32_t)stage * STGH;
            const uint32_t sB = sA + ASZH;

            uint32_t af[2][4][4], bf[2][2][4];
#pragma unroll
            for (int mt = 0; mt < 4; ++mt)
                ldsm4(af[0][mt], sA + swz(laRow + mt * 16, laKg));
            ldsm4(bf[0][0], sB + swz(lbRow,      lbKg));
            ldsm4(bf[0][1], sB + swz(lbRow + 16, lbKg));

#pragma unroll
            for (int ks = 0; ks < 4; ++ks) {
                const int cur = ks & 1;
                if (ks < 3) {
                    const int kg = 2 * (ks + 1);
#pragma unroll
                    for (int mt = 0; mt < 4; ++mt)
                        ldsm4(af[cur ^ 1][mt],
                              sA + swz(laRow + mt * 16, kg + laKg));
                    ldsm4(bf[cur ^ 1][0], sB + swz(lbRow,      kg + lbKg));
                    ldsm4(bf[cur ^ 1][1], sB + swz(lbRow + 16, kg + lbKg));
                }
#pragma unroll
                for (int mt = 0; mt < 4; ++mt)
#pragma unroll
                    for (int nt = 0; nt < 4; ++nt)
                        mma_f16(acc[mt][nt], af[cur][mt],
                                &bf[cur][nt >> 1][(nt & 1) * 2]);
            }

            if (++stage >= NSTAGE) stage = 0;
        }
        CP_WAIT0();

        // epilogue
#pragma unroll
        for (int mt = 0; mt < 4; ++mt) {
#pragma unroll
            for (int nt = 0; nt < 4; ++nt) {
                int row = bm + warpM + mt * 16 + (lane >> 2);
                int col = bn + warpN + nt * 8 + (lane & 3) * 2;
                if (HALF_OUT) {
                    __half* C = (__half*)Cv;
                    __half2 h0 = __floats2half2_rn(acc[mt][nt][0], acc[mt][nt][1]);
                    __half2 h1 = __floats2half2_rn(acc[mt][nt][2], acc[mt][nt][3]);
                    *reinterpret_cast<__half2*>(C + (size_t)row * N + col) = h0;
                    *reinterpret_cast<__half2*>(C + (size_t)(row + 8) * N + col) = h1;
                } else {
                    float* C = (float*)Cv;
                    float2 v0 = make_float2(acc[mt][nt][0], acc[mt][nt][1]);
                    float2 v1 = make_float2(acc[mt][nt][2], acc[mt][nt][3]);
                    *reinterpret_cast<float2*>(C + (size_t)row * N + col) = v0;
                    *reinterpret_cast<float2*>(C + (size_t)(row + 8) * N + col) = v1;
                }
            }
        }
        __syncthreads();   // tile transition: reads done before next prologue
    }
#undef ISSUE_STAGE
}

// ---------------------------------------------------------------------------
// Kernel 0: fused prologue.
// Block 0: coefficients. Blocks 1..768: weights -> fp16. Rest: x -> fp16
// (8 elements / thread, 16B stores).
// ---------------------------------------------------------------------------
#define WBLK (KV * HIDDEN / 256)            // 768
#define XBLK (MTOT * HIDDEN / 2048)         // 6144

__global__ void pre_kernel(const float* __restrict__ x,
                           const float* __restrict__ Wv,
                           const float* __restrict__ Wo) {
    const int b = blockIdx.x;
    if (b == 0) {
        __shared__ float warp_sum[8];
        const int t = threadIdx.x;
        const int lane = t & 31, warp = t >> 5;
        const float cc = -logf(10000.0f) / 384.0f;
        for (int d = 0; d <= DMAX; ++d) {
            float val = 0.f;
            for (int j = t; j < 384; j += 256)
                val += cosf((float)d * __expf(cc * (float)j));
#pragma unroll
            for (int o = 16; o; o >>= 1)
                val += __shfl_xor_sync(0xffffffffu, val, o);
            if (lane == 0) warp_sum[warp] = val;
            __syncthreads();
            if (t == 0) {
                float w = 0.f;
#pragma unroll
                for (int i = 0; i < 8; ++i) w += warp_sum[i];
                g_e[d] = expf(w - 384.0f);
            }
            __syncthreads();
        }
    } else if (b <= WBLK) {
        int i = (b - 1) * 256 + threadIdx.x;
        g_wvh[i] = __float2half_rn(Wv[i]);
        g_woh[i] = __float2half_rn(Wo[i]);
    } else {
        int i = (b - 1 - WBLK) * 2048 + threadIdx.x * 8;
        float4 v0 = *reinterpret_cast<const float4*>(x + i);
        float4 v1 = *reinterpret_cast<const float4*>(x + i + 4);
        __half2 h0 = __floats2half2_rn(v0.x, v0.y);
        __half2 h1 = __floats2half2_rn(v0.z, v0.w);
        __half2 h2 = __floats2half2_rn(v1.x, v1.y);
        __half2 h3 = __floats2half2_rn(v1.z, v1.w);
        uint4 o;
        o.x = *reinterpret_cast<uint32_t*>(&h0);
        o.y = *reinterpret_cast<uint32_t*>(&h1);
        o.z = *reinterpret_cast<uint32_t*>(&h2);
        o.w = *reinterpret_cast<uint32_t*>(&h3);
        *reinterpret_cast<uint4*>(g_xh + i) = o;
    }
}

// ---------------------------------------------------------------------------
// Kernel 2: softmax == normalized 15-tap convolution along seq (fp16 IO).
// Sliding window: 4 consecutive rows x 4 cols per thread; fp32 accumulate.
// ---------------------------------------------------------------------------
__global__ __launch_bounds__(256) void smooth_kernel() {
    const int NCG = KV / 4;                       // 64 col-groups of 4
    int idx = blockIdx.x * blockDim.x + threadIdx.x;
    if (idx >= (MTOT / 4) * NCG) return;
    const int mg = idx >> 6;
    const int c4 = (idx & 63) * 4;
    const int m0 = mg << 2;
    const int s0 = m0 & (SEQ - 1);

    float earr[15];
#pragma unroll
    for (int t = 0; t < 15; ++t) earr[t] = g_e[t < 7 ? 7 - t : t - 7];

    uint2 w[18];   // 4 fp16 per row
#pragma unroll
    for (int j = 0; j < 18; ++j) {
        int s = s0 - 7 + j;
        if (s >= 0 && s < SEQ)
            w[j] = *reinterpret_cast<const uint2*>(
                g_vh + (size_t)(m0 - 7 + j) * KV + c4);
        else
            w[j] = make_uint2(0u, 0u);
    }

#pragma unroll
    for (int i = 0; i < 4; ++i) {
        const int s = s0 + i;
        float acc[4] = {0.f, 0.f, 0.f, 0.f};
#pragma unroll
        for (int t = 0; t < 15; ++t) {
            const float e = earr[t];
            const uint32_t* uw = reinterpret_cast<const uint32_t*>(&w[i + t]);
#pragma unroll
            for (int p = 0; p < 2; ++p) {
                __half2 hh;
                *reinterpret_cast<uint32_t*>(&hh) = uw[p];
                float2 f = __half22float2(hh);
                acc[p * 2 + 0] += e * f.x;
                acc[p * 2 + 1] += e * f.y;
            }
        }
        float z = 1.0f;
#pragma unroll
        for (int d = 1; d <= DMAX; ++d) {
            if (s >= d)       z += g_e[d];
            if (s + d < SEQ)  z += g_e[d];
        }
        const float inv = 1.0f / z;
        __half2 o0 = __floats2half2_rn(acc[0] * inv, acc[1] * inv);
        __half2 o1 = __floats2half2_rn(acc[2] * inv, acc[3] * inv);
        uint2 o;
        o.x = *reinterpret_cast<uint32_t*>(&o0);
        o.y = *reinterpret_cast<uint32_t*>(&o1);
        *reinterpret_cast<uint2*>(g_ah + (size_t)(m0 + i) * KV + c4) = o;
    }
}

// ---------------------------------------------------------------------------
// Launch
// ---------------------------------------------------------------------------
extern "C" void kernel_launch(void* const* d_in, const int* in_sizes, int n_in,
                              void* d_out, int out_size) {
    const float* x  = (const float*)d_in[0];
    // d_in[1] = Wq, d_in[2] = Wk are dead (rope ignores its input)
    const float* Wv = (const float*)d_in[3];
    const float* Wo = (const float*)d_in[4];
    float* out = (float*)d_out;

    __half* vh_buf; cudaGetSymbolAddress((void**)&vh_buf, g_vh);
    __half* ah_buf; cudaGetSymbolAddress((void**)&ah_buf, g_ah);
    __half* xh_buf; cudaGetSymbolAddress((void**)&xh_buf, g_xh);
    __half* wv_buf; cudaGetSymbolAddress((void**)&wv_buf, g_wvh);
    __half* wo_buf; cudaGetSymbolAddress((void**)&wo_buf, g_woh);

    const int SMEM_BYTES = NSTAGE * STGH + 128;   // ~96 KB per CTA
    cudaFuncSetAttribute(gemm_fp16<true>,
                         cudaFuncAttributeMaxDynamicSharedMemorySize, SMEM_BYTES);
    cudaFuncSetAttribute(gemm_fp16<false>,
                         cudaFuncAttributeMaxDynamicSharedMemorySize, SMEM_BYTES);

    // 0) coefficients + fp16 pre-conversion of Wv, Wo, x (one launch)
    pre_kernel<<<1 + WBLK + XBLK, 256>>>(x, Wv, Wo);

    // 1) v = x @ Wv^T -> fp16  (tiles = 128x2 = 256 over 296 slots: 1 wave)
    gemm_fp16<true><<<256, 256, SMEM_BYTES>>>(xh_buf, wv_buf, vh_buf,
                                              MTOT, KV, HIDDEN);

    // 2) softmax(attn) @ v == normalized 15-tap convolution (fp16 -> fp16)
    {
        int n = (MTOT / 4) * (KV / 4);
        smooth_kernel<<<(n + 255) / 256, 256>>>();
    }

    // 3) out = a @ Wo^T -> fp32 (tiles = 128x6 = 768, persistent over 296)
    gemm_fp16<false><<<2 * NSM, 256, SMEM_BYTES>>>(ah_buf, wo_buf, out,
                                                   MTOT, HIDDEN, KV);
}